// round 7
// baseline (speedup 1.0000x reference)
#include <cuda_runtime.h>
#include <cuda_fp16.h>
#include <cstdint>
#include <math.h>

// Problem dims
#define B_    16
#define CIN   512
#define COUT  512
#define H_    64
#define W_    64
#define HW    4096
#define SDIM  32
#define OH    128
#define OW    128
#define EPS   1e-8f

// Scratch
__device__ float    g_s[B_ * CIN];
__device__ float    g_demod[B_ * COUT];
__device__ uint32_t g_wh[(size_t)B_ * COUT * CIN / 2];   // fp16 fragment-ordered weights (8 MB)
__device__ uint32_t g_xh[(size_t)B_ * (CIN / 2) * HW];   // half2-paired x (67 MB)
__device__ float    g_y[(size_t)B_ * COUT * HW];         // conv output (134 MB)

// ---------------------------------------------------------------------------
// Kernel A1: s[b,cin], demod[b,cout]. grid (8, 16), 256 threads.
// ---------------------------------------------------------------------------
__global__ __launch_bounds__(256) void mod_demod_kernel(
    const float* __restrict__ style,
    const float* __restrict__ conv_w,
    const float* __restrict__ mod_w,
    const float* __restrict__ mod_b)
{
    int og = blockIdx.x;
    int b  = blockIdx.y;
    int tid = threadIdx.x;
    __shared__ float s_sh[CIN];

    const float* st = style + b * SDIM;
#pragma unroll
    for (int rep = 0; rep < 2; rep++) {
        int i = tid + rep * 256;
        float acc = mod_b[i];
        const float* mw = mod_w + i * SDIM;
#pragma unroll
        for (int k = 0; k < SDIM; k++) acc += st[k] * mw[k];
        s_sh[i] = acc;
        if (og == 0) g_s[b * CIN + i] = acc;
    }
    __syncthreads();

    int wid = tid >> 5, lane = tid & 31;
#pragma unroll
    for (int cc = 0; cc < 8; cc++) {
        int o = og * 64 + wid * 8 + cc;
        const float* cw = conv_w + (size_t)o * CIN;
        float sum = 0.f;
#pragma unroll
        for (int it = 0; it < 4; it++) {
            int k4 = lane + it * 32;
            float4 v = __ldg((const float4*)cw + k4);
            int k = k4 * 4;
            float t0 = v.x * s_sh[k], t1 = v.y * s_sh[k + 1];
            float t2 = v.z * s_sh[k + 2], t3 = v.w * s_sh[k + 3];
            sum += t0 * t0 + t1 * t1 + t2 * t2 + t3 * t3;
        }
#pragma unroll
        for (int off = 16; off; off >>= 1)
            sum += __shfl_xor_sync(0xFFFFFFFFu, sum, off);
        if (lane == 0) g_demod[b * COUT + o] = rsqrtf(sum + EPS);
    }
}

// ---------------------------------------------------------------------------
// Kernel A2: fp16 weights in m16n8k16 fragment order.
// chunk-block (b, ot, c) = 2048 uint32:  idx = fgrp*128 + lane*4 + r
// grid (16 c, 4 ot, 16 b), 256 threads.
// ---------------------------------------------------------------------------
__global__ __launch_bounds__(256) void wfrag_kernel(
    const float* __restrict__ conv_w)
{
    int c  = blockIdx.x;
    int ot = blockIdx.y;
    int b  = blockIdx.z;
    int tid = threadIdx.x;
    int lane = tid & 31, fg = tid >> 5;
    int gid = lane >> 2, tg = lane & 3;

    uint32_t* cb = g_wh + ((size_t)((b * 4 + ot) * 16 + c)) * 2048;

#pragma unroll
    for (int rep = 0; rep < 2; rep++) {
        int fgrp = fg + rep * 8;
        int g  = fgrp >> 3;
        int s  = (fgrp >> 2) & 1;
        int mt = fgrp & 3;
        int o0 = ot * 128 + g * 64 + mt * 16 + gid;
        int o1 = o0 + 8;
        int k0 = c * 32 + s * 16 + tg * 2;

        float d0 = __ldg(g_demod + b * COUT + o0);
        float d1 = __ldg(g_demod + b * COUT + o1);
        float s00 = __ldg(g_s + b * CIN + k0);
        float s01 = __ldg(g_s + b * CIN + k0 + 1);
        float s08 = __ldg(g_s + b * CIN + k0 + 8);
        float s09 = __ldg(g_s + b * CIN + k0 + 9);

        float2 w0a = __ldg((const float2*)(conv_w + (size_t)o0 * CIN + k0));
        float2 w0b = __ldg((const float2*)(conv_w + (size_t)o0 * CIN + k0 + 8));
        float2 w1a = __ldg((const float2*)(conv_w + (size_t)o1 * CIN + k0));
        float2 w1b = __ldg((const float2*)(conv_w + (size_t)o1 * CIN + k0 + 8));

        __half2 h0 = __floats2half2_rn(w0a.x * s00 * d0, w0a.y * s01 * d0);
        __half2 h1 = __floats2half2_rn(w1a.x * s00 * d1, w1a.y * s01 * d1);
        __half2 h2 = __floats2half2_rn(w0b.x * s08 * d0, w0b.y * s09 * d0);
        __half2 h3 = __floats2half2_rn(w1b.x * s08 * d1, w1b.y * s09 * d1);

        uint4 u;
        u.x = *(uint32_t*)&h0; u.y = *(uint32_t*)&h1;
        u.z = *(uint32_t*)&h2; u.w = *(uint32_t*)&h3;
        *(uint4*)(cb + fgrp * 128 + lane * 4) = u;
    }
}

// ---------------------------------------------------------------------------
// Kernel A3: x -> half2 k-pair layout.
// ---------------------------------------------------------------------------
__global__ __launch_bounds__(256) void xcvt_kernel(const float* __restrict__ x)
{
    unsigned t = blockIdx.x * 256u + threadIdx.x;
    unsigned p4 = t & 1023u;
    unsigned kp = (t >> 10) & 255u;
    unsigned b  = t >> 18;

    const float4* s0 = (const float4*)(x + ((size_t)b * CIN + 2 * kp) * HW) + p4;
    const float4* s1 = (const float4*)(x + ((size_t)b * CIN + 2 * kp + 1) * HW) + p4;
    float4 a = __ldg(s0);
    float4 c = __ldg(s1);

    __half2 h0 = __floats2half2_rn(a.x, c.x);
    __half2 h1 = __floats2half2_rn(a.y, c.y);
    __half2 h2 = __floats2half2_rn(a.z, c.z);
    __half2 h3 = __floats2half2_rn(a.w, c.w);
    uint4 u;
    u.x = *(uint32_t*)&h0; u.y = *(uint32_t*)&h1;
    u.z = *(uint32_t*)&h2; u.w = *(uint32_t*)&h3;
    ((uint4*)(g_xh + ((size_t)b * 256 + kp) * HW))[p4] = u;
}

// ---------------------------------------------------------------------------
// Kernel B: batched GEMM, mma.sync.m16n8k16.f16 (fp32 accum).
// CTA 128x128. k-chunk 64 (4 mma k-steps), 3-stage cp.async, ONE sync/iter.
// A: fragment-ordered (LDS.128). B: [32 kp][136 half2] (conflict-free).
// ---------------------------------------------------------------------------
#define BSTRH 136
#define A_U32 4096                    // per stage (k=64 chunk = 2 blocks of 2048)
#define B_U32 (32 * BSTRH)            // 4352
#define STAGE_U32 (A_U32 + B_U32)     // 8448
#define NSTAGE 3
#define SM_GEMM_BYTES (NSTAGE * STAGE_U32 * 4)   // 101376

__device__ __forceinline__ uint32_t smem_u32(const void* p) {
    uint32_t a;
    asm("{ .reg .u64 t; cvta.to.shared.u64 t, %1; cvt.u32.u64 %0, t; }" : "=r"(a) : "l"(p));
    return a;
}

__global__ __launch_bounds__(256, 2) void gemm_mma(void)
{
    extern __shared__ uint32_t smu[];

    int tid = threadIdx.x;
    int wid = tid >> 5, lane = tid & 31;
    int gid = lane >> 2, tg = lane & 3;
    int b = blockIdx.z, oTile = blockIdx.y * 128, pTile = blockIdx.x * 128;
    int g = wid >> 2, wn = (wid & 3) * 32;

    const uint32_t* aglob = g_wh + ((size_t)((b * 4 + blockIdx.y) * 16)) * 2048;
    const uint32_t* xh    = g_xh + (size_t)b * 256 * HW + pTile;

    uint32_t sm_u = smem_u32(smu);
    // B cp.async: row = tid>>3 (kp 0..31), col = (tid&7)*16 u32
    int bkr = tid >> 3, bpc = (tid & 7) * 16;

    auto issue = [&](int ch) {
        int buf = ch % NSTAGE;
        uint32_t stage = sm_u + buf * STAGE_U32 * 4;
        // A: 4096 contiguous u32 per chunk; thread copies 64B
        const uint32_t* as_ = aglob + ch * 4096 + tid * 16;
        uint32_t ad = stage + tid * 64;
#pragma unroll
        for (int j = 0; j < 4; j++)
            asm volatile("cp.async.cg.shared.global [%0], [%1], 16;"
                         :: "r"(ad + j * 16), "l"(as_ + j * 4) : "memory");
        // B: 32 kp-rows x 128 u32
        const uint32_t* bs_ = xh + (size_t)(ch * 32 + bkr) * HW + bpc;
        uint32_t bd = stage + (A_U32 + bkr * BSTRH + bpc) * 4;
#pragma unroll
        for (int j = 0; j < 4; j++)
            asm volatile("cp.async.cg.shared.global [%0], [%1], 16;"
                         :: "r"(bd + j * 16), "l"(bs_ + j * 4) : "memory");
        asm volatile("cp.async.commit_group;" ::: "memory");
    };

    float c[4][4][4];
#pragma unroll
    for (int mt = 0; mt < 4; mt++)
#pragma unroll
        for (int nt = 0; nt < 4; nt++)
#pragma unroll
            for (int q = 0; q < 4; q++) c[mt][nt][q] = 0.f;

    issue(0); issue(1);

    const int NCH = CIN / 64;   // 8
    for (int ch = 0; ch < NCH; ch++) {
        if (ch + 1 < NCH) {
            asm volatile("cp.async.wait_group 1;" ::: "memory");
        } else {
            asm volatile("cp.async.wait_group 0;" ::: "memory");
        }
        __syncthreads();
        // Safe: issue targets buf (ch-1)%3; the barrier above guarantees all
        // warps finished compute(ch-1).
        if (ch + 2 < NCH) issue(ch + 2);

        int buf = ch % NSTAGE;
        const uint32_t* Ab = smu + buf * STAGE_U32;
        const uint32_t* Bb = smu + buf * STAGE_U32 + A_U32;

#pragma unroll
        for (int s = 0; s < 4; s++) {
            uint32_t af[4][4], bf[4][2];
            const uint32_t* Abs = Ab + (s >> 1) * 2048 + g * 1024 + (s & 1) * 512;
#pragma unroll
            for (int mt = 0; mt < 4; mt++) {
                uint4 av = *(const uint4*)(Abs + mt * 128 + lane * 4);
                af[mt][0] = av.x; af[mt][1] = av.y; af[mt][2] = av.z; af[mt][3] = av.w;
            }
#pragma unroll
            for (int nt = 0; nt < 4; nt++) {
                int nb = wn + nt * 8 + gid;
                bf[nt][0] = Bb[(s * 8 + tg) * BSTRH + nb];
                bf[nt][1] = Bb[(s * 8 + tg + 4) * BSTRH + nb];
            }
#pragma unroll
            for (int mt = 0; mt < 4; mt++)
#pragma unroll
                for (int nt = 0; nt < 4; nt++) {
                    asm volatile(
                        "mma.sync.aligned.m16n8k16.row.col.f32.f16.f16.f32 "
                        "{%0,%1,%2,%3}, {%4,%5,%6,%7}, {%8,%9}, {%0,%1,%2,%3};"
                        : "+f"(c[mt][nt][0]), "+f"(c[mt][nt][1]),
                          "+f"(c[mt][nt][2]), "+f"(c[mt][nt][3])
                        : "r"(af[mt][0]), "r"(af[mt][1]), "r"(af[mt][2]), "r"(af[mt][3]),
                          "r"(bf[nt][0]), "r"(bf[nt][1]));
                }
        }
    }

    float* yb = g_y + (size_t)b * COUT * HW;
#pragma unroll
    for (int mt = 0; mt < 4; mt++) {
        int r0 = oTile + g * 64 + mt * 16 + gid;
        int r1 = r0 + 8;
#pragma unroll
        for (int nt = 0; nt < 4; nt++) {
            int col = pTile + wn + nt * 8 + tg * 2;
            *(float2*)(yb + (size_t)r0 * HW + col) = make_float2(c[mt][nt][0], c[mt][nt][1]);
            *(float2*)(yb + (size_t)r1 * HW + col) = make_float2(c[mt][nt][2], c[mt][nt][3]);
        }
    }
}

// ---------------------------------------------------------------------------
// Kernel C: bilinear x2 upsample, smem-tiled. One block per (b,c) image.
// ---------------------------------------------------------------------------
__global__ __launch_bounds__(256) void upsample_kernel(float* __restrict__ out)
{
    __shared__ float ssm[64 * 68];
    unsigned c = blockIdx.x & 511u;
    unsigned b = blockIdx.x >> 9;
    int tid = threadIdx.x;
    int wid = tid >> 5, lane = tid & 31;

    const float4* src = (const float4*)(g_y + ((size_t)b * COUT + c) * HW);
#pragma unroll
    for (int j = 0; j < 4; j++) {
        int idx = tid + j * 256;
        int row = idx >> 4, col4 = idx & 15;
        *(float4*)(ssm + row * 68 + col4 * 4) = __ldg(src + idx);
    }
    __syncthreads();

    float* outp = out + ((size_t)b * COUT + c) * OH * OW;
#pragma unroll
    for (int i = 0; i < 16; i++) {
        int oy = i * 8 + wid;
        float fy  = oy * 0.5f - 0.25f;
        float y0f = floorf(fy);
        float wy  = fy - y0f;
        int iy0 = max(0, (int)y0f);
        int iy1 = min(63, (int)y0f + 1);
        const float* r0 = ssm + iy0 * 68;
        const float* r1 = ssm + iy1 * 68;
        float* orow = outp + (size_t)oy * OW;
#pragma unroll
        for (int seg = 0; seg < 2; seg++) {
            int xc = lane + seg * 32;
            int xm = max(0, xc - 1);
            int xp = min(63, xc + 1);
            float vm = r0[xm] + wy * (r1[xm] - r0[xm]);
            float vc = r0[xc] + wy * (r1[xc] - r0[xc]);
            float vp = r0[xp] + wy * (r1[xp] - r0[xp]);
            *(float2*)(orow + 2 * xc) =
                make_float2(0.25f * vm + 0.75f * vc, 0.75f * vc + 0.25f * vp);
        }
    }
}

// ---------------------------------------------------------------------------
extern "C" void kernel_launch(void* const* d_in, const int* in_sizes, int n_in,
                              void* d_out, int out_size)
{
    const float* x      = (const float*)d_in[0];
    const float* style  = (const float*)d_in[1];
    const float* conv_w = (const float*)d_in[2];
    const float* mod_w  = (const float*)d_in[3];
    const float* mod_b  = (const float*)d_in[4];
    float* out = (float*)d_out;

    cudaFuncSetAttribute(gemm_mma, cudaFuncAttributeMaxDynamicSharedMemorySize, SM_GEMM_BYTES);

    dim3 mgrid(8, 16);
    mod_demod_kernel<<<mgrid, 256>>>(style, conv_w, mod_w, mod_b);

    dim3 fgrid(16, 4, 16);
    wfrag_kernel<<<fgrid, 256>>>(conv_w);

    xcvt_kernel<<<16384, 256>>>(x);

    dim3 ggrid(HW / 128, COUT / 128, B_);   // (32, 4, 16)
    gemm_mma<<<ggrid, 256, SM_GEMM_BYTES>>>();

    upsample_kernel<<<B_ * COUT, 256>>>(out);
}

// round 8
// speedup vs baseline: 1.1232x; 1.1232x over previous
#include <cuda_runtime.h>
#include <cuda_fp16.h>
#include <cstdint>
#include <math.h>

// Problem dims
#define B_    16
#define CIN   512
#define COUT  512
#define H_    64
#define W_    64
#define HW    4096
#define SDIM  32
#define OH    128
#define OW    128
#define EPS   1e-8f

// Scratch
__device__ float    g_s[B_ * CIN];
__device__ float    g_demod[B_ * COUT];
__device__ uint32_t g_wh[(size_t)B_ * COUT * CIN / 2];   // fp16 A-fragment-ordered weights (8 MB)
__device__ uint4    g_xf[(size_t)B_ * 16 * 512 * 32];    // fp16 B-fragment-ordered x (67 MB)
__device__ float    g_y[(size_t)B_ * COUT * HW];         // conv output (134 MB)

// ---------------------------------------------------------------------------
// Kernel A1: s[b,cin], demod[b,cout]. grid (8, 16), 256 threads.
// ---------------------------------------------------------------------------
__global__ __launch_bounds__(256) void mod_demod_kernel(
    const float* __restrict__ style,
    const float* __restrict__ conv_w,
    const float* __restrict__ mod_w,
    const float* __restrict__ mod_b)
{
    int og = blockIdx.x;
    int b  = blockIdx.y;
    int tid = threadIdx.x;
    __shared__ float s_sh[CIN];

    const float* st = style + b * SDIM;
#pragma unroll
    for (int rep = 0; rep < 2; rep++) {
        int i = tid + rep * 256;
        float acc = mod_b[i];
        const float* mw = mod_w + i * SDIM;
#pragma unroll
        for (int k = 0; k < SDIM; k++) acc += st[k] * mw[k];
        s_sh[i] = acc;
        if (og == 0) g_s[b * CIN + i] = acc;
    }
    __syncthreads();

    int wid = tid >> 5, lane = tid & 31;
#pragma unroll
    for (int cc = 0; cc < 8; cc++) {
        int o = og * 64 + wid * 8 + cc;
        const float* cw = conv_w + (size_t)o * CIN;
        float sum = 0.f;
#pragma unroll
        for (int it = 0; it < 4; it++) {
            int k4 = lane + it * 32;
            float4 v = __ldg((const float4*)cw + k4);
            int k = k4 * 4;
            float t0 = v.x * s_sh[k], t1 = v.y * s_sh[k + 1];
            float t2 = v.z * s_sh[k + 2], t3 = v.w * s_sh[k + 3];
            sum += t0 * t0 + t1 * t1 + t2 * t2 + t3 * t3;
        }
#pragma unroll
        for (int off = 16; off; off >>= 1)
            sum += __shfl_xor_sync(0xFFFFFFFFu, sum, off);
        if (lane == 0) g_demod[b * COUT + o] = rsqrtf(sum + EPS);
    }
}

// ---------------------------------------------------------------------------
// Kernel A2: fp16 weights in m16n8k16 A-fragment order (as in R6).
// ---------------------------------------------------------------------------
__global__ __launch_bounds__(256) void wfrag_kernel(
    const float* __restrict__ conv_w)
{
    int c  = blockIdx.x;
    int ot = blockIdx.y;
    int b  = blockIdx.z;
    int tid = threadIdx.x;
    int lane = tid & 31, fg = tid >> 5;
    int gid = lane >> 2, tg = lane & 3;

    uint32_t* cb = g_wh + ((size_t)((b * 4 + ot) * 16 + c)) * 2048;

#pragma unroll
    for (int rep = 0; rep < 2; rep++) {
        int fgrp = fg + rep * 8;
        int g  = fgrp >> 3;
        int s  = (fgrp >> 2) & 1;
        int mt = fgrp & 3;
        int o0 = ot * 128 + g * 64 + mt * 16 + gid;
        int o1 = o0 + 8;
        int k0 = c * 32 + s * 16 + tg * 2;

        float d0 = __ldg(g_demod + b * COUT + o0);
        float d1 = __ldg(g_demod + b * COUT + o1);
        float s00 = __ldg(g_s + b * CIN + k0);
        float s01 = __ldg(g_s + b * CIN + k0 + 1);
        float s08 = __ldg(g_s + b * CIN + k0 + 8);
        float s09 = __ldg(g_s + b * CIN + k0 + 9);

        float2 w0a = __ldg((const float2*)(conv_w + (size_t)o0 * CIN + k0));
        float2 w0b = __ldg((const float2*)(conv_w + (size_t)o0 * CIN + k0 + 8));
        float2 w1a = __ldg((const float2*)(conv_w + (size_t)o1 * CIN + k0));
        float2 w1b = __ldg((const float2*)(conv_w + (size_t)o1 * CIN + k0 + 8));

        __half2 h0 = __floats2half2_rn(w0a.x * s00 * d0, w0a.y * s01 * d0);
        __half2 h1 = __floats2half2_rn(w1a.x * s00 * d1, w1a.y * s01 * d1);
        __half2 h2 = __floats2half2_rn(w0b.x * s08 * d0, w0b.y * s09 * d0);
        __half2 h3 = __floats2half2_rn(w1b.x * s08 * d1, w1b.y * s09 * d1);

        uint4 u;
        u.x = *(uint32_t*)&h0; u.y = *(uint32_t*)&h1;
        u.z = *(uint32_t*)&h2; u.w = *(uint32_t*)&h3;
        *(uint4*)(cb + fgrp * 128 + lane * 4) = u;
    }
}

// ---------------------------------------------------------------------------
// Kernel A3: x -> B-fragment order.
// g_xf[((b*16 + c)*512 + n8)*32 + lane] = uint4 where lane = (p&7)*4 + tg,
//   n8 = p>>3, component j (x,y,z,w): half2( x[2*kpj][p], x[2*kpj+1][p] ),
//   kpj = c*16 + tg + 4*j  (rows 2kpj = c*32 + 2*tg + 8*j).
// grid 16384 blocks x 256 threads: blk = (b*16 + c)*64 + seg.
// ---------------------------------------------------------------------------
__global__ __launch_bounds__(256) void xcvt_kernel(const float* __restrict__ x)
{
    unsigned blk = blockIdx.x;
    unsigned seg = blk & 63u;
    unsigned c   = (blk >> 6) & 15u;
    unsigned b   = blk >> 10;

    unsigned t  = seg * 256u + threadIdx.x;   // 0..16383
    unsigned tg = t & 3u;
    unsigned p  = t >> 2;                     // 0..4095

    const float* xb = x + (size_t)b * CIN * HW + p;
    unsigned rbase = c * 32 + 2 * tg;

    uint4 u;
    {
        float lo = __ldg(xb + (size_t)(rbase + 0) * HW);
        float hi = __ldg(xb + (size_t)(rbase + 1) * HW);
        __half2 h = __floats2half2_rn(lo, hi); u.x = *(uint32_t*)&h;
    }
    {
        float lo = __ldg(xb + (size_t)(rbase + 8) * HW);
        float hi = __ldg(xb + (size_t)(rbase + 9) * HW);
        __half2 h = __floats2half2_rn(lo, hi); u.y = *(uint32_t*)&h;
    }
    {
        float lo = __ldg(xb + (size_t)(rbase + 16) * HW);
        float hi = __ldg(xb + (size_t)(rbase + 17) * HW);
        __half2 h = __floats2half2_rn(lo, hi); u.z = *(uint32_t*)&h;
    }
    {
        float lo = __ldg(xb + (size_t)(rbase + 24) * HW);
        float hi = __ldg(xb + (size_t)(rbase + 25) * HW);
        __half2 h = __floats2half2_rn(lo, hi); u.w = *(uint32_t*)&h;
    }

    unsigned n8 = p >> 3;
    unsigned lane_out = (p & 7u) * 4u + tg;
    g_xf[((size_t)(b * 16 + c) * 512 + n8) * 32 + lane_out] = u;
}

// ---------------------------------------------------------------------------
// Kernel B: batched GEMM, mma.sync.m16n8k16.f16. R6 mainloop shape
// (chunk 32, 4 stages, issue -> wait 3 -> sync -> compute -> sync).
// A and B both fragment-ordered: 8 + 4 LDS.128 per chunk per warp.
// ---------------------------------------------------------------------------
#define A_U32 2048
#define B_U32 2048
#define STAGE_U32 (A_U32 + B_U32)     // 4096
#define NSTAGE 4
#define SM_GEMM_BYTES (NSTAGE * STAGE_U32 * 4)   // 65536

__device__ __forceinline__ uint32_t smem_u32(const void* p) {
    uint32_t a;
    asm("{ .reg .u64 t; cvta.to.shared.u64 t, %1; cvt.u32.u64 %0, t; }" : "=r"(a) : "l"(p));
    return a;
}

__global__ __launch_bounds__(256, 2) void gemm_mma(void)
{
    extern __shared__ uint32_t smu[];

    int tid = threadIdx.x;
    int wid = tid >> 5, lane = tid & 31;
    int gid = lane >> 2, tg = lane & 3;
    int b = blockIdx.z, oTile = blockIdx.y * 128, pTile = blockIdx.x * 128;
    int g = wid >> 2, wn = (wid & 3) * 32, wnb = (wid & 3) * 4;

    const uint32_t* aglob = g_wh + ((size_t)((b * 4 + blockIdx.y) * 16)) * 2048;
    const uint4*    bglob = g_xf + (size_t)b * 262144 + (size_t)(pTile >> 3) * 32;

    uint32_t sm_u = smem_u32(smu);

    auto issue = [&](int ch) {
        int buf = ch & (NSTAGE - 1);
        uint32_t stage = sm_u + buf * STAGE_U32 * 4;
        const uint32_t* as_ = aglob + ch * 2048 + tid * 8;
        uint32_t ad = stage + tid * 32;
        asm volatile("cp.async.cg.shared.global [%0], [%1], 16;" :: "r"(ad),      "l"(as_)     : "memory");
        asm volatile("cp.async.cg.shared.global [%0], [%1], 16;" :: "r"(ad + 16), "l"(as_ + 4) : "memory");
        const uint4* bs_ = bglob + (size_t)ch * 16384 + tid * 2;
        uint32_t bd = stage + A_U32 * 4 + tid * 32;
        asm volatile("cp.async.cg.shared.global [%0], [%1], 16;" :: "r"(bd),      "l"(bs_)     : "memory");
        asm volatile("cp.async.cg.shared.global [%0], [%1], 16;" :: "r"(bd + 16), "l"(bs_ + 1) : "memory");
        asm volatile("cp.async.commit_group;" ::: "memory");
    };

    float c[4][4][4];
#pragma unroll
    for (int mt = 0; mt < 4; mt++)
#pragma unroll
        for (int nt = 0; nt < 4; nt++)
#pragma unroll
            for (int q = 0; q < 4; q++) c[mt][nt][q] = 0.f;

    issue(0); issue(1); issue(2);

    const int NCH = CIN / 32;   // 16
    for (int ch = 0; ch < NCH; ch++) {
        if (ch + 3 < NCH) {
            issue(ch + 3);
            asm volatile("cp.async.wait_group 3;" ::: "memory");
        } else if (ch + 2 < NCH) {
            asm volatile("cp.async.wait_group 2;" ::: "memory");
        } else if (ch + 1 < NCH) {
            asm volatile("cp.async.wait_group 1;" ::: "memory");
        } else {
            asm volatile("cp.async.wait_group 0;" ::: "memory");
        }
        __syncthreads();

        int buf = ch & (NSTAGE - 1);
        const uint32_t* Ab = smu + buf * STAGE_U32 + g * 1024;
        const uint4*    Bb = (const uint4*)(smu + buf * STAGE_U32 + A_U32);

        // B fragments for the whole chunk: 4 x LDS.128, reused across s-steps.
        uint4 bv[4];
#pragma unroll
        for (int nt = 0; nt < 4; nt++)
            bv[nt] = Bb[(wnb + nt) * 32 + lane];

#pragma unroll
        for (int s = 0; s < 2; s++) {
            uint32_t af[4][4];
#pragma unroll
            for (int mt = 0; mt < 4; mt++) {
                uint4 av = *(const uint4*)(Ab + (s * 4 + mt) * 128 + lane * 4);
                af[mt][0] = av.x; af[mt][1] = av.y; af[mt][2] = av.z; af[mt][3] = av.w;
            }
#pragma unroll
            for (int mt = 0; mt < 4; mt++)
#pragma unroll
                for (int nt = 0; nt < 4; nt++) {
                    uint32_t b0 = s ? bv[nt].z : bv[nt].x;
                    uint32_t b1 = s ? bv[nt].w : bv[nt].y;
                    asm volatile(
                        "mma.sync.aligned.m16n8k16.row.col.f32.f16.f16.f32 "
                        "{%0,%1,%2,%3}, {%4,%5,%6,%7}, {%8,%9}, {%0,%1,%2,%3};"
                        : "+f"(c[mt][nt][0]), "+f"(c[mt][nt][1]),
                          "+f"(c[mt][nt][2]), "+f"(c[mt][nt][3])
                        : "r"(af[mt][0]), "r"(af[mt][1]), "r"(af[mt][2]), "r"(af[mt][3]),
                          "r"(b0), "r"(b1));
                }
        }
        __syncthreads();
    }

    float* yb = g_y + (size_t)b * COUT * HW;
#pragma unroll
    for (int mt = 0; mt < 4; mt++) {
        int r0 = oTile + g * 64 + mt * 16 + gid;
        int r1 = r0 + 8;
#pragma unroll
        for (int nt = 0; nt < 4; nt++) {
            int col = pTile + wn + nt * 8 + tg * 2;
            *(float2*)(yb + (size_t)r0 * HW + col) = make_float2(c[mt][nt][0], c[mt][nt][1]);
            *(float2*)(yb + (size_t)r1 * HW + col) = make_float2(c[mt][nt][2], c[mt][nt][3]);
        }
    }
}

// ---------------------------------------------------------------------------
// Kernel C: bilinear x2 upsample, smem-tiled. One block per (b,c) image.
// ---------------------------------------------------------------------------
__global__ __launch_bounds__(256) void upsample_kernel(float* __restrict__ out)
{
    __shared__ float ssm[64 * 68];
    unsigned c = blockIdx.x & 511u;
    unsigned b = blockIdx.x >> 9;
    int tid = threadIdx.x;
    int wid = tid >> 5, lane = tid & 31;

    const float4* src = (const float4*)(g_y + ((size_t)b * COUT + c) * HW);
#pragma unroll
    for (int j = 0; j < 4; j++) {
        int idx = tid + j * 256;
        int row = idx >> 4, col4 = idx & 15;
        *(float4*)(ssm + row * 68 + col4 * 4) = __ldg(src + idx);
    }
    __syncthreads();

    float* outp = out + ((size_t)b * COUT + c) * OH * OW;
#pragma unroll
    for (int i = 0; i < 16; i++) {
        int oy = i * 8 + wid;
        float fy  = oy * 0.5f - 0.25f;
        float y0f = floorf(fy);
        float wy  = fy - y0f;
        int iy0 = max(0, (int)y0f);
        int iy1 = min(63, (int)y0f + 1);
        const float* r0 = ssm + iy0 * 68;
        const float* r1 = ssm + iy1 * 68;
        float* orow = outp + (size_t)oy * OW;
#pragma unroll
        for (int seg = 0; seg < 2; seg++) {
            int xc = lane + seg * 32;
            int xm = max(0, xc - 1);
            int xp = min(63, xc + 1);
            float vm = r0[xm] + wy * (r1[xm] - r0[xm]);
            float vc = r0[xc] + wy * (r1[xc] - r0[xc]);
            float vp = r0[xp] + wy * (r1[xp] - r0[xp]);
            *(float2*)(orow + 2 * xc) =
                make_float2(0.25f * vm + 0.75f * vc, 0.75f * vc + 0.25f * vp);
        }
    }
}

// ---------------------------------------------------------------------------
extern "C" void kernel_launch(void* const* d_in, const int* in_sizes, int n_in,
                              void* d_out, int out_size)
{
    const float* x      = (const float*)d_in[0];
    const float* style  = (const float*)d_in[1];
    const float* conv_w = (const float*)d_in[2];
    const float* mod_w  = (const float*)d_in[3];
    const float* mod_b  = (const float*)d_in[4];
    float* out = (float*)d_out;

    cudaFuncSetAttribute(gemm_mma, cudaFuncAttributeMaxDynamicSharedMemorySize, SM_GEMM_BYTES);

    dim3 mgrid(8, 16);
    mod_demod_kernel<<<mgrid, 256>>>(style, conv_w, mod_w, mod_b);

    dim3 fgrid(16, 4, 16);
    wfrag_kernel<<<fgrid, 256>>>(conv_w);

    xcvt_kernel<<<16384, 256>>>(x);

    dim3 ggrid(HW / 128, COUT / 128, B_);   // (32, 4, 16)
    gemm_mma<<<ggrid, 256, SM_GEMM_BYTES>>>();

    upsample_kernel<<<B_ * COUT, 256>>>(out);
}

// round 9
// speedup vs baseline: 1.1632x; 1.0356x over previous
#include <cuda_runtime.h>
#include <cuda_fp16.h>
#include <cstdint>
#include <math.h>

// Problem dims
#define B_    16
#define CIN   512
#define COUT  512
#define H_    64
#define W_    64
#define HW    4096
#define SDIM  32
#define OH    128
#define OW    128
#define EPS   1e-8f

// Scratch
__device__ float    g_s[B_ * CIN];
__device__ float    g_demod[B_ * COUT];
__device__ uint32_t g_wh[(size_t)B_ * COUT * CIN / 2];   // fp16 A-fragment-ordered weights (8 MB)
__device__ uint4    g_xf[(size_t)B_ * 16 * 512 * 32];    // fp16 B-fragment-ordered x (67 MB)
__device__ __half   g_yh[(size_t)B_ * COUT * HW];        // conv output, fp16 (67 MB)

// ---------------------------------------------------------------------------
// Kernel A1: s[b,cin], demod[b,cout]. grid (8, 16), 256 threads.
// ---------------------------------------------------------------------------
__global__ __launch_bounds__(256) void mod_demod_kernel(
    const float* __restrict__ style,
    const float* __restrict__ conv_w,
    const float* __restrict__ mod_w,
    const float* __restrict__ mod_b)
{
    int og = blockIdx.x;
    int b  = blockIdx.y;
    int tid = threadIdx.x;
    __shared__ float s_sh[CIN];

    const float* st = style + b * SDIM;
#pragma unroll
    for (int rep = 0; rep < 2; rep++) {
        int i = tid + rep * 256;
        float acc = mod_b[i];
        const float* mw = mod_w + i * SDIM;
#pragma unroll
        for (int k = 0; k < SDIM; k++) acc += st[k] * mw[k];
        s_sh[i] = acc;
        if (og == 0) g_s[b * CIN + i] = acc;
    }
    __syncthreads();

    int wid = tid >> 5, lane = tid & 31;
#pragma unroll
    for (int cc = 0; cc < 8; cc++) {
        int o = og * 64 + wid * 8 + cc;
        const float* cw = conv_w + (size_t)o * CIN;
        float sum = 0.f;
#pragma unroll
        for (int it = 0; it < 4; it++) {
            int k4 = lane + it * 32;
            float4 v = __ldg((const float4*)cw + k4);
            int k = k4 * 4;
            float t0 = v.x * s_sh[k], t1 = v.y * s_sh[k + 1];
            float t2 = v.z * s_sh[k + 2], t3 = v.w * s_sh[k + 3];
            sum += t0 * t0 + t1 * t1 + t2 * t2 + t3 * t3;
        }
#pragma unroll
        for (int off = 16; off; off >>= 1)
            sum += __shfl_xor_sync(0xFFFFFFFFu, sum, off);
        if (lane == 0) g_demod[b * COUT + o] = rsqrtf(sum + EPS);
    }
}

// ---------------------------------------------------------------------------
// Kernel A2: fp16 weights in m16n8k16 A-fragment order.
// ---------------------------------------------------------------------------
__global__ __launch_bounds__(256) void wfrag_kernel(
    const float* __restrict__ conv_w)
{
    int c  = blockIdx.x;
    int ot = blockIdx.y;
    int b  = blockIdx.z;
    int tid = threadIdx.x;
    int lane = tid & 31, fg = tid >> 5;
    int gid = lane >> 2, tg = lane & 3;

    uint32_t* cb = g_wh + ((size_t)((b * 4 + ot) * 16 + c)) * 2048;

#pragma unroll
    for (int rep = 0; rep < 2; rep++) {
        int fgrp = fg + rep * 8;
        int g  = fgrp >> 3;
        int s  = (fgrp >> 2) & 1;
        int mt = fgrp & 3;
        int o0 = ot * 128 + g * 64 + mt * 16 + gid;
        int o1 = o0 + 8;
        int k0 = c * 32 + s * 16 + tg * 2;

        float d0 = __ldg(g_demod + b * COUT + o0);
        float d1 = __ldg(g_demod + b * COUT + o1);
        float s00 = __ldg(g_s + b * CIN + k0);
        float s01 = __ldg(g_s + b * CIN + k0 + 1);
        float s08 = __ldg(g_s + b * CIN + k0 + 8);
        float s09 = __ldg(g_s + b * CIN + k0 + 9);

        float2 w0a = __ldg((const float2*)(conv_w + (size_t)o0 * CIN + k0));
        float2 w0b = __ldg((const float2*)(conv_w + (size_t)o0 * CIN + k0 + 8));
        float2 w1a = __ldg((const float2*)(conv_w + (size_t)o1 * CIN + k0));
        float2 w1b = __ldg((const float2*)(conv_w + (size_t)o1 * CIN + k0 + 8));

        __half2 h0 = __floats2half2_rn(w0a.x * s00 * d0, w0a.y * s01 * d0);
        __half2 h1 = __floats2half2_rn(w1a.x * s00 * d1, w1a.y * s01 * d1);
        __half2 h2 = __floats2half2_rn(w0b.x * s08 * d0, w0b.y * s09 * d0);
        __half2 h3 = __floats2half2_rn(w1b.x * s08 * d1, w1b.y * s09 * d1);

        uint4 u;
        u.x = *(uint32_t*)&h0; u.y = *(uint32_t*)&h1;
        u.z = *(uint32_t*)&h2; u.w = *(uint32_t*)&h3;
        *(uint4*)(cb + fgrp * 128 + lane * 4) = u;
    }
}

// ---------------------------------------------------------------------------
// Kernel A3: x -> B-fragment order (same as R8).
// ---------------------------------------------------------------------------
__global__ __launch_bounds__(256) void xcvt_kernel(const float* __restrict__ x)
{
    unsigned blk = blockIdx.x;
    unsigned seg = blk & 63u;
    unsigned c   = (blk >> 6) & 15u;
    unsigned b   = blk >> 10;

    unsigned t  = seg * 256u + threadIdx.x;
    unsigned tg = t & 3u;
    unsigned p  = t >> 2;

    const float* xb = x + (size_t)b * CIN * HW + p;
    unsigned rbase = c * 32 + 2 * tg;

    uint4 u;
    {
        float lo = __ldg(xb + (size_t)(rbase + 0) * HW);
        float hi = __ldg(xb + (size_t)(rbase + 1) * HW);
        __half2 h = __floats2half2_rn(lo, hi); u.x = *(uint32_t*)&h;
    }
    {
        float lo = __ldg(xb + (size_t)(rbase + 8) * HW);
        float hi = __ldg(xb + (size_t)(rbase + 9) * HW);
        __half2 h = __floats2half2_rn(lo, hi); u.y = *(uint32_t*)&h;
    }
    {
        float lo = __ldg(xb + (size_t)(rbase + 16) * HW);
        float hi = __ldg(xb + (size_t)(rbase + 17) * HW);
        __half2 h = __floats2half2_rn(lo, hi); u.z = *(uint32_t*)&h;
    }
    {
        float lo = __ldg(xb + (size_t)(rbase + 24) * HW);
        float hi = __ldg(xb + (size_t)(rbase + 25) * HW);
        __half2 h = __floats2half2_rn(lo, hi); u.w = *(uint32_t*)&h;
    }

    unsigned n8 = p >> 3;
    unsigned lane_out = (p & 7u) * 4u + tg;
    g_xf[((size_t)(b * 16 + c) * 512 + n8) * 32 + lane_out] = u;
}

// ---------------------------------------------------------------------------
// Kernel B: batched GEMM, mma.sync.m16n8k16.f16 — R8 mainloop, fp16 output.
// ---------------------------------------------------------------------------
#define A_U32 2048
#define B_U32 2048
#define STAGE_U32 (A_U32 + B_U32)
#define NSTAGE 4
#define SM_GEMM_BYTES (NSTAGE * STAGE_U32 * 4)   // 65536

__device__ __forceinline__ uint32_t smem_u32(const void* p) {
    uint32_t a;
    asm("{ .reg .u64 t; cvta.to.shared.u64 t, %1; cvt.u32.u64 %0, t; }" : "=r"(a) : "l"(p));
    return a;
}

__global__ __launch_bounds__(256, 2) void gemm_mma(void)
{
    extern __shared__ uint32_t smu[];

    int tid = threadIdx.x;
    int wid = tid >> 5, lane = tid & 31;
    int gid = lane >> 2, tg = lane & 3;
    int b = blockIdx.z, oTile = blockIdx.y * 128, pTile = blockIdx.x * 128;
    int g = wid >> 2, wn = (wid & 3) * 32, wnb = (wid & 3) * 4;

    const uint32_t* aglob = g_wh + ((size_t)((b * 4 + blockIdx.y) * 16)) * 2048;
    const uint4*    bglob = g_xf + (size_t)b * 262144 + (size_t)(pTile >> 3) * 32;

    uint32_t sm_u = smem_u32(smu);

    auto issue = [&](int ch) {
        int buf = ch & (NSTAGE - 1);
        uint32_t stage = sm_u + buf * STAGE_U32 * 4;
        const uint32_t* as_ = aglob + ch * 2048 + tid * 8;
        uint32_t ad = stage + tid * 32;
        asm volatile("cp.async.cg.shared.global [%0], [%1], 16;" :: "r"(ad),      "l"(as_)     : "memory");
        asm volatile("cp.async.cg.shared.global [%0], [%1], 16;" :: "r"(ad + 16), "l"(as_ + 4) : "memory");
        const uint4* bs_ = bglob + (size_t)ch * 16384 + tid * 2;
        uint32_t bd = stage + A_U32 * 4 + tid * 32;
        asm volatile("cp.async.cg.shared.global [%0], [%1], 16;" :: "r"(bd),      "l"(bs_)     : "memory");
        asm volatile("cp.async.cg.shared.global [%0], [%1], 16;" :: "r"(bd + 16), "l"(bs_ + 1) : "memory");
        asm volatile("cp.async.commit_group;" ::: "memory");
    };

    float c[4][4][4];
#pragma unroll
    for (int mt = 0; mt < 4; mt++)
#pragma unroll
        for (int nt = 0; nt < 4; nt++)
#pragma unroll
            for (int q = 0; q < 4; q++) c[mt][nt][q] = 0.f;

    issue(0); issue(1); issue(2);

    const int NCH = CIN / 32;   // 16
    for (int ch = 0; ch < NCH; ch++) {
        if (ch + 3 < NCH) {
            issue(ch + 3);
            asm volatile("cp.async.wait_group 3;" ::: "memory");
        } else if (ch + 2 < NCH) {
            asm volatile("cp.async.wait_group 2;" ::: "memory");
        } else if (ch + 1 < NCH) {
            asm volatile("cp.async.wait_group 1;" ::: "memory");
        } else {
            asm volatile("cp.async.wait_group 0;" ::: "memory");
        }
        __syncthreads();

        int buf = ch & (NSTAGE - 1);
        const uint32_t* Ab = smu + buf * STAGE_U32 + g * 1024;
        const uint4*    Bb = (const uint4*)(smu + buf * STAGE_U32 + A_U32);

        uint4 bv[4];
#pragma unroll
        for (int nt = 0; nt < 4; nt++)
            bv[nt] = Bb[(wnb + nt) * 32 + lane];

#pragma unroll
        for (int s = 0; s < 2; s++) {
            uint32_t af[4][4];
#pragma unroll
            for (int mt = 0; mt < 4; mt++) {
                uint4 av = *(const uint4*)(Ab + (s * 4 + mt) * 128 + lane * 4);
                af[mt][0] = av.x; af[mt][1] = av.y; af[mt][2] = av.z; af[mt][3] = av.w;
            }
#pragma unroll
            for (int mt = 0; mt < 4; mt++)
#pragma unroll
                for (int nt = 0; nt < 4; nt++) {
                    uint32_t b0 = s ? bv[nt].z : bv[nt].x;
                    uint32_t b1 = s ? bv[nt].w : bv[nt].y;
                    asm volatile(
                        "mma.sync.aligned.m16n8k16.row.col.f32.f16.f16.f32 "
                        "{%0,%1,%2,%3}, {%4,%5,%6,%7}, {%8,%9}, {%0,%1,%2,%3};"
                        : "+f"(c[mt][nt][0]), "+f"(c[mt][nt][1]),
                          "+f"(c[mt][nt][2]), "+f"(c[mt][nt][3])
                        : "r"(af[mt][0]), "r"(af[mt][1]), "r"(af[mt][2]), "r"(af[mt][3]),
                          "r"(b0), "r"(b1));
                }
        }
        __syncthreads();
    }

    // Epilogue: fp16 stores (half the traffic of R8).
    __half* yb = g_yh + (size_t)b * COUT * HW;
#pragma unroll
    for (int mt = 0; mt < 4; mt++) {
        int r0 = oTile + g * 64 + mt * 16 + gid;
        int r1 = r0 + 8;
#pragma unroll
        for (int nt = 0; nt < 4; nt++) {
            int col = pTile + wn + nt * 8 + tg * 2;
            __half2 h0 = __floats2half2_rn(c[mt][nt][0], c[mt][nt][1]);
            __half2 h1 = __floats2half2_rn(c[mt][nt][2], c[mt][nt][3]);
            *(__half2*)(yb + (size_t)r0 * HW + col) = h0;
            *(__half2*)(yb + (size_t)r1 * HW + col) = h1;
        }
    }
}

// ---------------------------------------------------------------------------
// Kernel C: bilinear x2 upsample from fp16 y, smem-tiled, fp32 out.
// ---------------------------------------------------------------------------
__global__ __launch_bounds__(256) void upsample_kernel(float* __restrict__ out)
{
    __shared__ float ssm[64 * 68];
    unsigned c = blockIdx.x & 511u;
    unsigned b = blockIdx.x >> 9;
    int tid = threadIdx.x;
    int wid = tid >> 5, lane = tid & 31;

    // Load 4096 halfs (8 KB) as 512 uint4; each thread: 2 loads, 8 halfs each.
    const uint4* src = (const uint4*)(g_yh + ((size_t)b * COUT + c) * HW);
#pragma unroll
    for (int j = 0; j < 2; j++) {
        int idx = tid + j * 256;          // 0..511
        int row = idx >> 3, col8 = idx & 7;
        uint4 v = __ldg(src + idx);
        float* dst = ssm + row * 68 + col8 * 8;
        float2 f0 = __half22float2(*(__half2*)&v.x);
        float2 f1 = __half22float2(*(__half2*)&v.y);
        float2 f2 = __half22float2(*(__half2*)&v.z);
        float2 f3 = __half22float2(*(__half2*)&v.w);
        dst[0] = f0.x; dst[1] = f0.y; dst[2] = f1.x; dst[3] = f1.y;
        dst[4] = f2.x; dst[5] = f2.y; dst[6] = f3.x; dst[7] = f3.y;
    }
    __syncthreads();

    float* outp = out + ((size_t)b * COUT + c) * OH * OW;
#pragma unroll
    for (int i = 0; i < 16; i++) {
        int oy = i * 8 + wid;
        float fy  = oy * 0.5f - 0.25f;
        float y0f = floorf(fy);
        float wy  = fy - y0f;
        int iy0 = max(0, (int)y0f);
        int iy1 = min(63, (int)y0f + 1);
        const float* r0 = ssm + iy0 * 68;
        const float* r1 = ssm + iy1 * 68;
        float* orow = outp + (size_t)oy * OW;
#pragma unroll
        for (int seg = 0; seg < 2; seg++) {
            int xc = lane + seg * 32;
            int xm = max(0, xc - 1);
            int xp = min(63, xc + 1);
            float vm = r0[xm] + wy * (r1[xm] - r0[xm]);
            float vc = r0[xc] + wy * (r1[xc] - r0[xc]);
            float vp = r0[xp] + wy * (r1[xp] - r0[xp]);
            *(float2*)(orow + 2 * xc) =
                make_float2(0.25f * vm + 0.75f * vc, 0.75f * vc + 0.25f * vp);
        }
    }
}

// ---------------------------------------------------------------------------
extern "C" void kernel_launch(void* const* d_in, const int* in_sizes, int n_in,
                              void* d_out, int out_size)
{
    const float* x      = (const float*)d_in[0];
    const float* style  = (const float*)d_in[1];
    const float* conv_w = (const float*)d_in[2];
    const float* mod_w  = (const float*)d_in[3];
    const float* mod_b  = (const float*)d_in[4];
    float* out = (float*)d_out;

    cudaFuncSetAttribute(gemm_mma, cudaFuncAttributeMaxDynamicSharedMemorySize, SM_GEMM_BYTES);

    dim3 mgrid(8, 16);
    mod_demod_kernel<<<mgrid, 256>>>(style, conv_w, mod_w, mod_b);

    dim3 fgrid(16, 4, 16);
    wfrag_kernel<<<fgrid, 256>>>(conv_w);

    xcvt_kernel<<<16384, 256>>>(x);

    dim3 ggrid(HW / 128, COUT / 128, B_);   // (32, 4, 16)
    gemm_mma<<<ggrid, 256, SM_GEMM_BYTES>>>();

    upsample_kernel<<<B_ * COUT, 256>>>(out);
}

// round 10
// speedup vs baseline: 1.2309x; 1.0582x over previous
#include <cuda_runtime.h>
#include <cuda_fp16.h>
#include <cstdint>
#include <math.h>

// Problem dims
#define B_    16
#define CIN   512
#define COUT  512
#define H_    64
#define W_    64
#define HW    4096
#define SDIM  32
#define OH    128
#define OW    128
#define EPS   1e-8f

// Scratch
__device__ float    g_s[B_ * CIN];
__device__ float    g_demod[B_ * COUT];
__device__ uint32_t g_wh[(size_t)B_ * COUT * CIN / 2];   // fp16 A-fragment-ordered weights (8 MB)
__device__ uint4    g_xf[(size_t)B_ * 16 * 512 * 32];    // fp16 B-fragment-ordered x (67 MB)
__device__ __half   g_yh[(size_t)B_ * COUT * HW];        // conv output, fp16 (67 MB)

// ---------------------------------------------------------------------------
// Kernel A1: s[b,cin], demod[b,cout]. grid (8, 16), 256 threads.
// ---------------------------------------------------------------------------
__global__ __launch_bounds__(256) void mod_demod_kernel(
    const float* __restrict__ style,
    const float* __restrict__ conv_w,
    const float* __restrict__ mod_w,
    const float* __restrict__ mod_b)
{
    int og = blockIdx.x;
    int b  = blockIdx.y;
    int tid = threadIdx.x;
    __shared__ float s_sh[CIN];

    const float* st = style + b * SDIM;
#pragma unroll
    for (int rep = 0; rep < 2; rep++) {
        int i = tid + rep * 256;
        float acc = mod_b[i];
        const float* mw = mod_w + i * SDIM;
#pragma unroll
        for (int k = 0; k < SDIM; k++) acc += st[k] * mw[k];
        s_sh[i] = acc;
        if (og == 0) g_s[b * CIN + i] = acc;
    }
    __syncthreads();

    int wid = tid >> 5, lane = tid & 31;
#pragma unroll
    for (int cc = 0; cc < 8; cc++) {
        int o = og * 64 + wid * 8 + cc;
        const float* cw = conv_w + (size_t)o * CIN;
        float sum = 0.f;
#pragma unroll
        for (int it = 0; it < 4; it++) {
            int k4 = lane + it * 32;
            float4 v = __ldg((const float4*)cw + k4);
            int k = k4 * 4;
            float t0 = v.x * s_sh[k], t1 = v.y * s_sh[k + 1];
            float t2 = v.z * s_sh[k + 2], t3 = v.w * s_sh[k + 3];
            sum += t0 * t0 + t1 * t1 + t2 * t2 + t3 * t3;
        }
#pragma unroll
        for (int off = 16; off; off >>= 1)
            sum += __shfl_xor_sync(0xFFFFFFFFu, sum, off);
        if (lane == 0) g_demod[b * COUT + o] = rsqrtf(sum + EPS);
    }
}

// ---------------------------------------------------------------------------
// Kernel A2: fp16 weights in m16n8k16 A-fragment order.
// ---------------------------------------------------------------------------
__global__ __launch_bounds__(256) void wfrag_kernel(
    const float* __restrict__ conv_w)
{
    int c  = blockIdx.x;
    int ot = blockIdx.y;
    int b  = blockIdx.z;
    int tid = threadIdx.x;
    int lane = tid & 31, fg = tid >> 5;
    int gid = lane >> 2, tg = lane & 3;

    uint32_t* cb = g_wh + ((size_t)((b * 4 + ot) * 16 + c)) * 2048;

#pragma unroll
    for (int rep = 0; rep < 2; rep++) {
        int fgrp = fg + rep * 8;
        int g  = fgrp >> 3;
        int s  = (fgrp >> 2) & 1;
        int mt = fgrp & 3;
        int o0 = ot * 128 + g * 64 + mt * 16 + gid;
        int o1 = o0 + 8;
        int k0 = c * 32 + s * 16 + tg * 2;

        float d0 = __ldg(g_demod + b * COUT + o0);
        float d1 = __ldg(g_demod + b * COUT + o1);
        float s00 = __ldg(g_s + b * CIN + k0);
        float s01 = __ldg(g_s + b * CIN + k0 + 1);
        float s08 = __ldg(g_s + b * CIN + k0 + 8);
        float s09 = __ldg(g_s + b * CIN + k0 + 9);

        float2 w0a = __ldg((const float2*)(conv_w + (size_t)o0 * CIN + k0));
        float2 w0b = __ldg((const float2*)(conv_w + (size_t)o0 * CIN + k0 + 8));
        float2 w1a = __ldg((const float2*)(conv_w + (size_t)o1 * CIN + k0));
        float2 w1b = __ldg((const float2*)(conv_w + (size_t)o1 * CIN + k0 + 8));

        __half2 h0 = __floats2half2_rn(w0a.x * s00 * d0, w0a.y * s01 * d0);
        __half2 h1 = __floats2half2_rn(w1a.x * s00 * d1, w1a.y * s01 * d1);
        __half2 h2 = __floats2half2_rn(w0b.x * s08 * d0, w0b.y * s09 * d0);
        __half2 h3 = __floats2half2_rn(w1b.x * s08 * d1, w1b.y * s09 * d1);

        uint4 u;
        u.x = *(uint32_t*)&h0; u.y = *(uint32_t*)&h1;
        u.z = *(uint32_t*)&h2; u.w = *(uint32_t*)&h3;
        *(uint4*)(cb + fgrp * 128 + lane * 4) = u;
    }
}

// ---------------------------------------------------------------------------
// Kernel A3: x -> B-fragment order.
// ---------------------------------------------------------------------------
__global__ __launch_bounds__(256) void xcvt_kernel(const float* __restrict__ x)
{
    unsigned blk = blockIdx.x;
    unsigned seg = blk & 63u;
    unsigned c   = (blk >> 6) & 15u;
    unsigned b   = blk >> 10;

    unsigned t  = seg * 256u + threadIdx.x;
    unsigned tg = t & 3u;
    unsigned p  = t >> 2;

    const float* xb = x + (size_t)b * CIN * HW + p;
    unsigned rbase = c * 32 + 2 * tg;

    uint4 u;
    {
        float lo = __ldg(xb + (size_t)(rbase + 0) * HW);
        float hi = __ldg(xb + (size_t)(rbase + 1) * HW);
        __half2 h = __floats2half2_rn(lo, hi); u.x = *(uint32_t*)&h;
    }
    {
        float lo = __ldg(xb + (size_t)(rbase + 8) * HW);
        float hi = __ldg(xb + (size_t)(rbase + 9) * HW);
        __half2 h = __floats2half2_rn(lo, hi); u.y = *(uint32_t*)&h;
    }
    {
        float lo = __ldg(xb + (size_t)(rbase + 16) * HW);
        float hi = __ldg(xb + (size_t)(rbase + 17) * HW);
        __half2 h = __floats2half2_rn(lo, hi); u.z = *(uint32_t*)&h;
    }
    {
        float lo = __ldg(xb + (size_t)(rbase + 24) * HW);
        float hi = __ldg(xb + (size_t)(rbase + 25) * HW);
        __half2 h = __floats2half2_rn(lo, hi); u.w = *(uint32_t*)&h;
    }

    unsigned n8 = p >> 3;
    unsigned lane_out = (p & 7u) * 4u + tg;
    g_xf[((size_t)(b * 16 + c) * 512 + n8) * 32 + lane_out] = u;
}

// ---------------------------------------------------------------------------
// Kernel B: batched GEMM, mma.sync.m16n8k16.f16.
// 5-stage cp.async pipeline, ONE __syncthreads per chunk:
//   wait_group 3 -> sync -> issue(ch+4) -> compute(ch)
// issue(ch+4) writes buf (ch-1)%5, protected by the sync (all warps done
// computing ch-1). In-flight groups target bufs (ch+1..ch+4)%5, never ch%5.
// ---------------------------------------------------------------------------
#define A_U32 2048
#define B_U32 2048
#define STAGE_U32 (A_U32 + B_U32)
#define NSTAGE 5
#define SM_GEMM_BYTES (NSTAGE * STAGE_U32 * 4)   // 81920

__device__ __forceinline__ uint32_t smem_u32(const void* p) {
    uint32_t a;
    asm("{ .reg .u64 t; cvta.to.shared.u64 t, %1; cvt.u32.u64 %0, t; }" : "=r"(a) : "l"(p));
    return a;
}

__global__ __launch_bounds__(256, 2) void gemm_mma(void)
{
    extern __shared__ uint32_t smu[];

    int tid = threadIdx.x;
    int wid = tid >> 5, lane = tid & 31;
    int gid = lane >> 2, tg = lane & 3;
    int b = blockIdx.z, oTile = blockIdx.y * 128, pTile = blockIdx.x * 128;
    int g = wid >> 2, wn = (wid & 3) * 32, wnb = (wid & 3) * 4;

    const uint32_t* aglob = g_wh + ((size_t)((b * 4 + blockIdx.y) * 16)) * 2048;
    const uint4*    bglob = g_xf + (size_t)b * 262144 + (size_t)(pTile >> 3) * 32;

    uint32_t sm_u = smem_u32(smu);

    auto issue = [&](int ch) {
        int buf = ch % NSTAGE;
        uint32_t stage = sm_u + buf * STAGE_U32 * 4;
        const uint32_t* as_ = aglob + ch * 2048 + tid * 8;
        uint32_t ad = stage + tid * 32;
        asm volatile("cp.async.cg.shared.global [%0], [%1], 16;" :: "r"(ad),      "l"(as_)     : "memory");
        asm volatile("cp.async.cg.shared.global [%0], [%1], 16;" :: "r"(ad + 16), "l"(as_ + 4) : "memory");
        const uint4* bs_ = bglob + (size_t)ch * 16384 + tid * 2;
        uint32_t bd = stage + A_U32 * 4 + tid * 32;
        asm volatile("cp.async.cg.shared.global [%0], [%1], 16;" :: "r"(bd),      "l"(bs_)     : "memory");
        asm volatile("cp.async.cg.shared.global [%0], [%1], 16;" :: "r"(bd + 16), "l"(bs_ + 1) : "memory");
        asm volatile("cp.async.commit_group;" ::: "memory");
    };

    float c[4][4][4];
#pragma unroll
    for (int mt = 0; mt < 4; mt++)
#pragma unroll
        for (int nt = 0; nt < 4; nt++)
#pragma unroll
            for (int q = 0; q < 4; q++) c[mt][nt][q] = 0.f;

    issue(0); issue(1); issue(2); issue(3);

    const int NCH = CIN / 32;   // 16
    for (int ch = 0; ch < NCH; ch++) {
        // Ensure chunk ch has landed. Issued through min(ch+3, NCH-1).
        if (ch + 3 < NCH) {
            asm volatile("cp.async.wait_group 3;" ::: "memory");
        } else if (ch + 2 < NCH) {
            asm volatile("cp.async.wait_group 2;" ::: "memory");
        } else if (ch + 1 < NCH) {
            asm volatile("cp.async.wait_group 1;" ::: "memory");
        } else {
            asm volatile("cp.async.wait_group 0;" ::: "memory");
        }
        __syncthreads();

        if (ch + 4 < NCH) issue(ch + 4);

        int buf = ch % NSTAGE;
        const uint32_t* Ab = smu + buf * STAGE_U32 + g * 1024;
        const uint4*    Bb = (const uint4*)(smu + buf * STAGE_U32 + A_U32);

        uint4 bv[4];
#pragma unroll
        for (int nt = 0; nt < 4; nt++)
            bv[nt] = Bb[(wnb + nt) * 32 + lane];

#pragma unroll
        for (int s = 0; s < 2; s++) {
            uint32_t af[4][4];
#pragma unroll
            for (int mt = 0; mt < 4; mt++) {
                uint4 av = *(const uint4*)(Ab + (s * 4 + mt) * 128 + lane * 4);
                af[mt][0] = av.x; af[mt][1] = av.y; af[mt][2] = av.z; af[mt][3] = av.w;
            }
#pragma unroll
            for (int mt = 0; mt < 4; mt++)
#pragma unroll
                for (int nt = 0; nt < 4; nt++) {
                    uint32_t b0 = s ? bv[nt].z : bv[nt].x;
                    uint32_t b1 = s ? bv[nt].w : bv[nt].y;
                    asm volatile(
                        "mma.sync.aligned.m16n8k16.row.col.f32.f16.f16.f32 "
                        "{%0,%1,%2,%3}, {%4,%5,%6,%7}, {%8,%9}, {%0,%1,%2,%3};"
                        : "+f"(c[mt][nt][0]), "+f"(c[mt][nt][1]),
                          "+f"(c[mt][nt][2]), "+f"(c[mt][nt][3])
                        : "r"(af[mt][0]), "r"(af[mt][1]), "r"(af[mt][2]), "r"(af[mt][3]),
                          "r"(b0), "r"(b1));
                }
        }
    }

    // Epilogue: fp16 stores.
    __half* yb = g_yh + (size_t)b * COUT * HW;
#pragma unroll
    for (int mt = 0; mt < 4; mt++) {
        int r0 = oTile + g * 64 + mt * 16 + gid;
        int r1 = r0 + 8;
#pragma unroll
        for (int nt = 0; nt < 4; nt++) {
            int col = pTile + wn + nt * 8 + tg * 2;
            __half2 h0 = __floats2half2_rn(c[mt][nt][0], c[mt][nt][1]);
            __half2 h1 = __floats2half2_rn(c[mt][nt][2], c[mt][nt][3]);
            *(__half2*)(yb + (size_t)r0 * HW + col) = h0;
            *(__half2*)(yb + (size_t)r1 * HW + col) = h1;
        }
    }
}

// ---------------------------------------------------------------------------
// Kernel C: bilinear x2 upsample from fp16 y, smem-tiled, fp32 out.
// ---------------------------------------------------------------------------
__global__ __launch_bounds__(256) void upsample_kernel(float* __restrict__ out)
{
    __shared__ float ssm[64 * 68];
    unsigned c = blockIdx.x & 511u;
    unsigned b = blockIdx.x >> 9;
    int tid = threadIdx.x;
    int wid = tid >> 5, lane = tid & 31;

    const uint4* src = (const uint4*)(g_yh + ((size_t)b * COUT + c) * HW);
#pragma unroll
    for (int j = 0; j < 2; j++) {
        int idx = tid + j * 256;
        int row = idx >> 3, col8 = idx & 7;
        uint4 v = __ldg(src + idx);
        float* dst = ssm + row * 68 + col8 * 8;
        float2 f0 = __half22float2(*(__half2*)&v.x);
        float2 f1 = __half22float2(*(__half2*)&v.y);
        float2 f2 = __half22float2(*(__half2*)&v.z);
        float2 f3 = __half22float2(*(__half2*)&v.w);
        dst[0] = f0.x; dst[1] = f0.y; dst[2] = f1.x; dst[3] = f1.y;
        dst[4] = f2.x; dst[5] = f2.y; dst[6] = f3.x; dst[7] = f3.y;
    }
    __syncthreads();

    float* outp = out + ((size_t)b * COUT + c) * OH * OW;
#pragma unroll
    for (int i = 0; i < 16; i++) {
        int oy = i * 8 + wid;
        float fy  = oy * 0.5f - 0.25f;
        float y0f = floorf(fy);
        float wy  = fy - y0f;
        int iy0 = max(0, (int)y0f);
        int iy1 = min(63, (int)y0f + 1);
        const float* r0 = ssm + iy0 * 68;
        const float* r1 = ssm + iy1 * 68;
        float* orow = outp + (size_t)oy * OW;
#pragma unroll
        for (int seg = 0; seg < 2; seg++) {
            int xc = lane + seg * 32;
            int xm = max(0, xc - 1);
            int xp = min(63, xc + 1);
            float vm = r0[xm] + wy * (r1[xm] - r0[xm]);
            float vc = r0[xc] + wy * (r1[xc] - r0[xc]);
            float vp = r0[xp] + wy * (r1[xp] - r0[xp]);
            *(float2*)(orow + 2 * xc) =
                make_float2(0.25f * vm + 0.75f * vc, 0.75f * vc + 0.25f * vp);
        }
    }
}

// ---------------------------------------------------------------------------
extern "C" void kernel_launch(void* const* d_in, const int* in_sizes, int n_in,
                              void* d_out, int out_size)
{
    const float* x      = (const float*)d_in[0];
    const float* style  = (const float*)d_in[1];
    const float* conv_w = (const float*)d_in[2];
    const float* mod_w  = (const float*)d_in[3];
    const float* mod_b  = (const float*)d_in[4];
    float* out = (float*)d_out;

    cudaFuncSetAttribute(gemm_mma, cudaFuncAttributeMaxDynamicSharedMemorySize, SM_GEMM_BYTES);

    dim3 mgrid(8, 16);
    mod_demod_kernel<<<mgrid, 256>>>(style, conv_w, mod_w, mod_b);

    dim3 fgrid(16, 4, 16);
    wfrag_kernel<<<fgrid, 256>>>(conv_w);

    xcvt_kernel<<<16384, 256>>>(x);

    dim3 ggrid(HW / 128, COUT / 128, B_);   // (32, 4, 16)
    gemm_mma<<<ggrid, 256, SM_GEMM_BYTES>>>();

    upsample_kernel<<<B_ * COUT, 256>>>(out);
}